// round 1
// baseline (speedup 1.0000x reference)
#include <cuda_runtime.h>

#define DX 256
#define DY 256
#define DZ 32
#define VOL (DX * DY * DZ)   // 2,097,152

// Ping-pong scratch (8 MB). Device globals are the allowed scratch mechanism.
__device__ float g_scratch[VOL];

// Neighbor offset tables (row, col) for k = 0..7, derived from the reference's
// ZeroPad2d shift set: rows [+1,+1,+1,0,0,-1,-1,-1], cols [+1,0,-1,+1,-1,+1,0,-1].
//
// DIR = 0: rows->x, cols->y (guidance channels 0..7,  fixed z)
// DIR = 1: rows->x, cols->z (guidance channels 8..15, fixed y)
// DIR = 2: rows->y, cols->z (guidance channels 16..23, fixed x)
template <int DIR>
__global__ __launch_bounds__(256) void prop_step(
    const float* __restrict__ G,     // guidance base [24, 256, 256, 32]
    const float* __restrict__ src,   // [256, 256, 32]
    float* __restrict__ dst)         // [256, 256, 32]
{
    const int tid = blockIdx.x * 256 + threadIdx.x;
    const int z = tid & (DZ - 1);
    const int y = (tid >> 5) & (DY - 1);
    const int x = tid >> 13;

    const float bc = src[tid];

    float gv[8], bv[8];
    float asum = 0.0f;

    constexpr int DR[8] = { 1, 1, 1, 0, 0, -1, -1, -1 };
    constexpr int DC[8] = { 1, 0, -1, 1, -1, 1, 0, -1 };

#pragma unroll
    for (int k = 0; k < 8; ++k) {
        int nx, ny, nz;
        bool ok;
        if (DIR == 0) {
            nx = x + DR[k]; ny = y + DC[k]; nz = z;
            ok = ((unsigned)nx < DX) & ((unsigned)ny < DY);
        } else if (DIR == 1) {
            nx = x + DR[k]; ny = y; nz = z + DC[k];
            ok = ((unsigned)nx < DX) & ((unsigned)nz < DZ);
        } else {
            nx = x; ny = y + DR[k]; nz = z + DC[k];
            ok = ((unsigned)ny < DY) & ((unsigned)nz < DZ);
        }
        float g = 0.0f, b = 0.0f;
        if (ok) {
            const int nidx = (nx * DY + ny) * DZ + nz;
            g = __ldg(&G[(DIR * 8 + k) * VOL + nidx]);
            b = __ldg(&src[nidx]);
        }
        gv[k] = g;
        bv[k] = b;
        asum += fabsf(g);
    }

    const float inv = 1.0f / asum;
    float ws = 0.0f, gs = 0.0f;
#pragma unroll
    for (int k = 0; k < 8; ++k) {
        ws += gv[k] * bv[k];
        gs += gv[k];
    }

    dst[tid] = (1.0f - gs * inv) * bc + ws * inv;
}

extern "C" void kernel_launch(void* const* d_in, const int* in_sizes, int n_in,
                              void* d_out, int out_size)
{
    const float* G    = (const float*)d_in[0];  // guidance [24,256,256,32]
    const float* blur = (const float*)d_in[1];  // blur [1,256,256,32]
    float* out = (float*)d_out;

    void* sp = nullptr;
    cudaGetSymbolAddress(&sp, g_scratch);
    float* scr = (float*)sp;

    const int grid = VOL / 256;

    // 9 steps: dir 0,1,2 repeated 3x. Ping-pong out/scr so step 9 writes d_out.
    // Write targets: out, scr, out, scr, out, scr, out, scr, out.
    const float* src = blur;
    float* bufs[2] = { out, scr };
    int w = 0;

    for (int it = 0; it < 3; ++it) {
        prop_step<0><<<grid, 256>>>(G, src, bufs[w]);
        src = bufs[w]; w ^= 1;
        prop_step<1><<<grid, 256>>>(G, src, bufs[w]);
        src = bufs[w]; w ^= 1;
        prop_step<2><<<grid, 256>>>(G, src, bufs[w]);
        src = bufs[w]; w ^= 1;
    }
}